// round 5
// baseline (speedup 1.0000x reference)
#include <cuda_runtime.h>
#include <cuda_bf16.h>
#include <cstdint>

#define DD    128
#define BD    16384
#define SQ36  0.28867513459481287f

// ---- dynamic smem byte offsets ----
#define AOP    0           // bf16 A0 [128x128], pitch 256B, XOR swizzle (32KB)
#define WOP    32768       // bf16 W  (32KB). Bytes 0..65535 reused as fp32 comm after MMA.
#define VOFF   65536       // v[128] fp32
#define PSOFF  66048       // ps[256] fp32
#define SMEM_REQ 67584

__device__ __forceinline__ uint32_t smem_u32(const void* p) {
    uint32_t a;
    asm("{ .reg .u64 t; cvta.to.shared.u64 t, %1; cvt.u32.u64 %0, t; }" : "=r"(a) : "l"(p));
    return a;
}
__device__ __forceinline__ void ldsm_x4(uint32_t* r, uint32_t addr) {
    asm volatile("ldmatrix.sync.aligned.m8n8.x4.shared.b16 {%0,%1,%2,%3}, [%4];"
                 : "=r"(r[0]), "=r"(r[1]), "=r"(r[2]), "=r"(r[3]) : "r"(addr));
}
__device__ __forceinline__ void ldsm_x4t(uint32_t* r, uint32_t addr) {
    asm volatile("ldmatrix.sync.aligned.m8n8.x4.trans.shared.b16 {%0,%1,%2,%3}, [%4];"
                 : "=r"(r[0]), "=r"(r[1]), "=r"(r[2]), "=r"(r[3]) : "r"(addr));
}
__device__ __forceinline__ void mma16816(float* d, const uint32_t* a, const uint32_t* b) {
    asm volatile("mma.sync.aligned.m16n8k16.row.col.f32.bf16.bf16.f32 "
                 "{%0,%1,%2,%3}, {%4,%5,%6,%7}, {%8,%9}, {%0,%1,%2,%3};"
                 : "+f"(d[0]), "+f"(d[1]), "+f"(d[2]), "+f"(d[3])
                 : "r"(a[0]), "r"(a[1]), "r"(a[2]), "r"(a[3]), "r"(b[0]), "r"(b[1]));
}
// bf16 tile address (pitch 256B, 16B chunks XORed per 8 rows)
__device__ __forceinline__ uint32_t taddr(uint32_t base, int row, int col) {
    int chunk = (col >> 3) ^ (row & 7);
    return base + row * 256 + (chunk << 4);
}
// fp32 comm region address (pitch 512B, 16B chunks XORed per 32 rows)
__device__ __forceinline__ uint32_t caddr(int row, int col) {
    return (uint32_t)(row * 512 + ((((col >> 2) ^ (row & 31)) << 4)) + ((col & 3) << 2));
}
__device__ __forceinline__ uint32_t b2u(__nv_bfloat162 v) { return *reinterpret_cast<uint32_t*>(&v); }

__global__ __launch_bounds__(256, 2)
void magnus_kernel(const float* __restrict__ t0, const float* __restrict__ hp,
                   const float* __restrict__ y0,
                   const float* __restrict__ A0, const float* __restrict__ W,
                   float* __restrict__ out, int B)
{
    extern __shared__ char sm[];
    const uint32_t sb = smem_u32(sm);

    const int b    = blockIdx.x;
    const int tid  = threadIdx.x;
    const int lane = tid & 31;
    const int wid  = tid >> 5;

    const float h   = hp[0];
    const float t0b = t0[b];
    const float t1  = t0b + (0.5f - SQ36) * h;
    const float t2  = t0b + (0.5f + SQ36) * h;
    const float c12 = h * h * h * (1.0f / 12.0f);

    float* v  = (float*)(sm + VOFF);
    float* ps = (float*)(sm + PSOFF);

    // ---- Phase 1: stream A0,W -> bf16 tiles; emit A1,A2 to global ----
    const float4* A0g = (const float4*)(A0 + (size_t)b * BD);
    const float4* Wg  = (const float4*)(W  + (size_t)b * BD);
    float* o1base = out + (size_t)B * DD + (size_t)b * BD;
    float* o2base = o1base + (size_t)B * BD;
    float4* o1 = (float4*)o1base;
    float4* o2 = (float4*)o2base;

    #pragma unroll
    for (int it = 0; it < 16; ++it) {
        int i    = tid + 256 * it;
        int row  = i >> 5;
        float4 a = A0g[i];
        float4 w = Wg[i];
        float4 x1, x2;
        x1.x = fmaf(t1, w.x, a.x); x1.y = fmaf(t1, w.y, a.y);
        x1.z = fmaf(t1, w.z, a.z); x1.w = fmaf(t1, w.w, a.w);
        x2.x = fmaf(t2, w.x, a.x); x2.y = fmaf(t2, w.y, a.y);
        x2.z = fmaf(t2, w.z, a.z); x2.w = fmaf(t2, w.w, a.w);
        o1[i] = x1;
        o2[i] = x2;
        uint32_t off = (uint32_t)(row * 256 + ((((i & 31) >> 1) ^ (row & 7)) << 4) + ((i & 1) << 3));
        uint2 pa, pw;
        pa.x = b2u(__floats2bfloat162_rn(a.x, a.y)); pa.y = b2u(__floats2bfloat162_rn(a.z, a.w));
        pw.x = b2u(__floats2bfloat162_rn(w.x, w.y)); pw.y = b2u(__floats2bfloat162_rn(w.z, w.w));
        *(uint2*)(sm + AOP + off) = pa;
        *(uint2*)(sm + WOP + off) = pw;
    }
    __syncthreads();

    // ---- Phase 2: comm = A0@W + (-W)@A0; 2x4 warp grid, 64x32 tile/warp ----
    const uint32_t aA = sb + AOP;
    const uint32_t aW = sb + WOP;
    const int m0 = (wid >> 2) << 6;   // 0 or 64
    const int n0 = (wid & 3) << 5;    // 0,32,64,96
    const int arow = lane & 15;
    const int acol = (lane >> 4) << 3;

    float acc[4][4][4];
    #pragma unroll
    for (int mh = 0; mh < 4; ++mh)
        #pragma unroll
        for (int nt = 0; nt < 4; ++nt)
            #pragma unroll
            for (int r = 0; r < 4; ++r) acc[mh][nt][r] = 0.0f;

    #pragma unroll
    for (int k0 = 0; k0 < DD; k0 += 16) {
        uint32_t fa[4][4], fw[4][4];
        #pragma unroll
        for (int mh = 0; mh < 4; ++mh) {
            ldsm_x4(fa[mh], taddr(aA, m0 + 16 * mh + arow, k0 + acol));
            ldsm_x4(fw[mh], taddr(aW, m0 + 16 * mh + arow, k0 + acol));
            #pragma unroll
            for (int q = 0; q < 4; ++q) fw[mh][q] ^= 0x80008000u;   // -W
        }
        #pragma unroll
        for (int nn = 0; nn < 2; ++nn) {
            uint32_t bW[4], bA[4];
            ldsm_x4t(bW, taddr(aW, k0 + arow, n0 + 16 * nn + acol));
            ldsm_x4t(bA, taddr(aA, k0 + arow, n0 + 16 * nn + acol));
            #pragma unroll
            for (int mh = 0; mh < 4; ++mh) {
                mma16816(acc[mh][2 * nn],     fa[mh], bW);
                mma16816(acc[mh][2 * nn + 1], fa[mh], bW + 2);
                mma16816(acc[mh][2 * nn],     fw[mh], bA);
                mma16816(acc[mh][2 * nn + 1], fw[mh], bA + 2);
            }
        }
    }
    __syncthreads();   // all tile reads complete; safe to overwrite as comm

    // ---- Phase 3: store -c12*comm into reused smem (fp32, swizzled) ----
    {
        const int lr = lane >> 2;
        const int lc = (lane & 3) << 1;
        #pragma unroll
        for (int mh = 0; mh < 4; ++mh)
            #pragma unroll
            for (int nt = 0; nt < 4; ++nt)
                #pragma unroll
                for (int r = 0; r < 4; ++r) {
                    int row = m0 + 16 * mh + lr + ((r >> 1) << 3);
                    int col = n0 + 8 * nt + lc + (r & 1);
                    *(float*)(sm + caddr(row, col)) = -c12 * acc[mh][nt][r];
                }
    }
    __syncthreads();

    // ---- Phase 4: Omega row slice in regs: om = (h/2)(A1+A2) - c12*comm ----
    const int r = tid & 127;
    const int q = tid >> 7;              // 0..1, 64 cols each
    const float hh = 0.5f * h;

    const float4* a1r = (const float4*)(o1base + (size_t)r * DD + 64 * q);
    const float4* a2r = (const float4*)(o2base + (size_t)r * DD + 64 * q);

    float om[64];
    #pragma unroll
    for (int j = 0; j < 16; ++j) {
        float4 f1 = a1r[j];                       // L2-hot: written in phase 1
        float4 f2 = a2r[j];
        float4 cm = *(const float4*)(sm + (uint32_t)(r * 512 + (((16 * q + j) ^ (r & 31)) << 4)));
        om[4 * j + 0] = fmaf(hh, f1.x + f2.x, cm.x);
        om[4 * j + 1] = fmaf(hh, f1.y + f2.y, cm.y);
        om[4 * j + 2] = fmaf(hh, f1.z + f2.z, cm.z);
        om[4 * j + 3] = fmaf(hh, f1.w + f2.w, cm.w);
    }

    float yvreg = 0.0f;
    if (q == 0) {
        float y0i = y0[(size_t)b * DD + r];
        v[r]  = y0i;
        yvreg = y0i;
    }
    __syncthreads();

    #pragma unroll 1
    for (int k = 1; k <= 10; ++k) {
        const float4* vp = (const float4*)(v + 64 * q);
        float s0 = 0.f, s1 = 0.f, s2 = 0.f, s3 = 0.f;
        #pragma unroll
        for (int j = 0; j < 16; ++j) {
            float4 f = vp[j];
            s0 = fmaf(om[4 * j + 0], f.x, s0);
            s1 = fmaf(om[4 * j + 1], f.y, s1);
            s2 = fmaf(om[4 * j + 2], f.z, s2);
            s3 = fmaf(om[4 * j + 3], f.w, s3);
        }
        ps[(q << 7) + r] = (s0 + s1) + (s2 + s3);
        __syncthreads();
        if (q == 0) {
            float nv = (ps[r] + ps[128 + r]) * (1.0f / (float)k);
            v[r]   = nv;
            yvreg += nv;
        }
        __syncthreads();
    }

    if (q == 0) out[(size_t)b * DD + r] = yvreg;
}

extern "C" void kernel_launch(void* const* d_in, const int* in_sizes, int n_in,
                              void* d_out, int out_size) {
    const float* t0 = (const float*)d_in[0];
    const float* h  = (const float*)d_in[1];
    const float* y0 = (const float*)d_in[2];
    const float* A0 = (const float*)d_in[3];
    const float* W  = (const float*)d_in[4];
    const int B = in_sizes[0];

    cudaFuncSetAttribute(magnus_kernel, cudaFuncAttributeMaxDynamicSharedMemorySize, SMEM_REQ);
    magnus_kernel<<<B, 256, SMEM_REQ>>>(t0, h, y0, A0, W, (float*)d_out, B);
}

// round 6
// speedup vs baseline: 1.0224x; 1.0224x over previous
#include <cuda_runtime.h>
#include <cuda_bf16.h>
#include <cstdint>

#define DD    128
#define BD    16384
#define SQ36  0.28867513459481287f

// ---- dynamic smem byte offsets ----
#define RAWA  0            // fp32 A0 raw [128x128], pitch 512B, 16B-chunk XOR (row&7)
#define RAWW  65536        // fp32 W raw, same layout
#define TILES 131072       // bf16 A tile (32KB) + bf16 W tile (32KB); reused as fp32 comm (64KB)
#define WTILE (TILES + 32768)
#define VOFF  196608       // v[128] fp32
#define PSOFF 197120       // ps[512] fp32, layout [r*4+q]
#define SMEM_REQ 199680

__device__ __forceinline__ uint32_t smem_u32(const void* p) {
    uint32_t a;
    asm("{ .reg .u64 t; cvta.to.shared.u64 t, %1; cvt.u32.u64 %0, t; }" : "=r"(a) : "l"(p));
    return a;
}
__device__ __forceinline__ void ldsm_x4(uint32_t* r, uint32_t addr) {
    asm volatile("ldmatrix.sync.aligned.m8n8.x4.shared.b16 {%0,%1,%2,%3}, [%4];"
                 : "=r"(r[0]), "=r"(r[1]), "=r"(r[2]), "=r"(r[3]) : "r"(addr));
}
__device__ __forceinline__ void ldsm_x4t(uint32_t* r, uint32_t addr) {
    asm volatile("ldmatrix.sync.aligned.m8n8.x4.trans.shared.b16 {%0,%1,%2,%3}, [%4];"
                 : "=r"(r[0]), "=r"(r[1]), "=r"(r[2]), "=r"(r[3]) : "r"(addr));
}
__device__ __forceinline__ void mma16816(float* d, const uint32_t* a, const uint32_t* b) {
    asm volatile("mma.sync.aligned.m16n8k16.row.col.f32.bf16.bf16.f32 "
                 "{%0,%1,%2,%3}, {%4,%5,%6,%7}, {%8,%9}, {%0,%1,%2,%3};"
                 : "+f"(d[0]), "+f"(d[1]), "+f"(d[2]), "+f"(d[3])
                 : "r"(a[0]), "r"(a[1]), "r"(a[2]), "r"(a[3]), "r"(b[0]), "r"(b[1]));
}
__device__ __forceinline__ void cp16(uint32_t dst, const void* src) {
    asm volatile("cp.async.cg.shared.global [%0], [%1], 16;" :: "r"(dst), "l"(src));
}
// bf16 tile address (pitch 256B, 16B chunks XORed per 8 rows)
__device__ __forceinline__ uint32_t taddr(uint32_t base, int row, int col) {
    int chunk = (col >> 3) ^ (row & 7);
    return base + row * 256 + (chunk << 4);
}
__device__ __forceinline__ uint32_t b2u(__nv_bfloat162 v) { return *reinterpret_cast<uint32_t*>(&v); }

__global__ __launch_bounds__(512, 1)
void magnus_kernel(const float* __restrict__ t0, const float* __restrict__ hp,
                   const float* __restrict__ y0,
                   const float* __restrict__ A0, const float* __restrict__ Wm,
                   float* __restrict__ out, int B)
{
    extern __shared__ char sm[];
    const uint32_t sb = smem_u32(sm);

    const int tid  = threadIdx.x;
    const int lane = tid & 31;
    const int wid  = tid >> 5;

    const float h   = hp[0];
    const float c12 = h * h * h * (1.0f / 12.0f);

    float* v  = (float*)(sm + VOFF);
    float* ps = (float*)(sm + PSOFF);

    const int step = gridDim.x;
    int b = blockIdx.x;

    // ---- prime prefetch of batch b ----
    {
        const char* sA = (const char*)(A0 + (size_t)b * BD);
        const char* sW = (const char*)(Wm + (size_t)b * BD);
        #pragma unroll
        for (int it = 0; it < 8; ++it) {
            int i = tid + 512 * it;                     // 16B-chunk index (4096/matrix)
            int row = i >> 5, ch = i & 31;
            uint32_t off = (uint32_t)(row * 512 + ((ch ^ (row & 7)) << 4));
            cp16(sb + RAWA + off, sA + (size_t)i * 16);
            cp16(sb + RAWW + off, sW + (size_t)i * 16);
        }
        asm volatile("cp.async.commit_group;" ::: "memory");
    }

    for (; b < B; b += step) {
        const float t0b = t0[b];
        const float t1  = t0b + (0.5f - SQ36) * h;
        const float t2  = t0b + (0.5f + SQ36) * h;
        const float tm  = t0b + 0.5f * h;

        asm volatile("cp.async.wait_group 0;" ::: "memory");
        __syncthreads();

        // ---- Phase A: raw smem -> A1/A2 (STG) + bf16 tiles ----
        float* o1base = out + (size_t)B * DD + (size_t)b * BD;
        float* o2base = o1base + (size_t)B * BD;
        float4* o1 = (float4*)o1base;
        float4* o2 = (float4*)o2base;

        #pragma unroll
        for (int it = 0; it < 8; ++it) {
            int i = tid + 512 * it;
            int row = i >> 5, ch = i & 31;
            uint32_t roff = (uint32_t)(row * 512 + ((ch ^ (row & 7)) << 4));
            float4 a = *(const float4*)(sm + RAWA + roff);
            float4 w = *(const float4*)(sm + RAWW + roff);
            float4 x1, x2;
            x1.x = fmaf(t1, w.x, a.x); x1.y = fmaf(t1, w.y, a.y);
            x1.z = fmaf(t1, w.z, a.z); x1.w = fmaf(t1, w.w, a.w);
            x2.x = fmaf(t2, w.x, a.x); x2.y = fmaf(t2, w.y, a.y);
            x2.z = fmaf(t2, w.z, a.z); x2.w = fmaf(t2, w.w, a.w);
            o1[i] = x1;
            o2[i] = x2;
            uint32_t toff = (uint32_t)(row * 256 + (((ch >> 1) ^ (row & 7)) << 4) + ((i & 1) << 3));
            uint2 pa, pw;
            pa.x = b2u(__floats2bfloat162_rn(a.x, a.y)); pa.y = b2u(__floats2bfloat162_rn(a.z, a.w));
            pw.x = b2u(__floats2bfloat162_rn(w.x, w.y)); pw.y = b2u(__floats2bfloat162_rn(w.z, w.w));
            *(uint2*)(sm + TILES + toff) = pa;
            *(uint2*)(sm + WTILE + toff) = pw;
        }
        __syncthreads();

        // ---- Phase B: comm = A0@W + (-W)@A0; 4x4 warp grid, 32x32 tile/warp ----
        const uint32_t aA = sb + TILES;
        const uint32_t aW = sb + WTILE;
        const int m0 = (wid >> 2) << 5;
        const int n0 = (wid & 3) << 5;
        const int arow = lane & 15;
        const int acol = (lane >> 4) << 3;

        float acc[2][4][4];
        #pragma unroll
        for (int mh = 0; mh < 2; ++mh)
            #pragma unroll
            for (int nt = 0; nt < 4; ++nt)
                #pragma unroll
                for (int rr = 0; rr < 4; ++rr) acc[mh][nt][rr] = 0.0f;

        #pragma unroll
        for (int k0 = 0; k0 < DD; k0 += 16) {
            uint32_t aA1[4], aA2[4], aW1[4], aW2[4];
            ldsm_x4(aA1, taddr(aA, m0 + arow,      k0 + acol));
            ldsm_x4(aA2, taddr(aA, m0 + 16 + arow, k0 + acol));
            ldsm_x4(aW1, taddr(aW, m0 + arow,      k0 + acol));
            ldsm_x4(aW2, taddr(aW, m0 + 16 + arow, k0 + acol));
            #pragma unroll
            for (int qq = 0; qq < 4; ++qq) { aW1[qq] ^= 0x80008000u; aW2[qq] ^= 0x80008000u; }
            #pragma unroll
            for (int nn = 0; nn < 2; ++nn) {
                uint32_t bW[4], bA[4];
                ldsm_x4t(bW, taddr(aW, k0 + arow, n0 + 16 * nn + acol));
                ldsm_x4t(bA, taddr(aA, k0 + arow, n0 + 16 * nn + acol));
                mma16816(acc[0][2 * nn],     aA1, bW);
                mma16816(acc[0][2 * nn + 1], aA1, bW + 2);
                mma16816(acc[1][2 * nn],     aA2, bW);
                mma16816(acc[1][2 * nn + 1], aA2, bW + 2);
                mma16816(acc[0][2 * nn],     aW1, bA);
                mma16816(acc[0][2 * nn + 1], aW1, bA + 2);
                mma16816(acc[1][2 * nn],     aW2, bA);
                mma16816(acc[1][2 * nn + 1], aW2, bA + 2);
            }
        }
        __syncthreads();   // tile reads complete; TILES reusable as comm

        // ---- Phase C: -c12*comm -> TILES (fp32, pitch 512B, chunk XOR row&7); v init ----
        {
            const int lr = lane >> 2;
            const int lc = (lane & 3) << 1;
            #pragma unroll
            for (int mh = 0; mh < 2; ++mh)
                #pragma unroll
                for (int nt = 0; nt < 4; ++nt)
                    #pragma unroll
                    for (int half = 0; half < 2; ++half) {
                        int row = m0 + 16 * mh + lr + 8 * half;
                        int col = n0 + 8 * nt + lc;
                        uint32_t off = (uint32_t)(row * 512 + (((col >> 2) ^ (row & 7)) << 4) + ((col & 3) << 2));
                        float2 val;
                        val.x = -c12 * acc[mh][nt][2 * half];
                        val.y = -c12 * acc[mh][nt][2 * half + 1];
                        *(float2*)(sm + TILES + off) = val;
                    }
        }
        if (tid < DD) v[tid] = y0[(size_t)b * DD + tid];
        __syncthreads();

        // ---- Phase D: Omega row-slice into regs from raw smem + comm smem ----
        const int r = tid >> 2;
        const int q = tid & 3;
        float om[32];
        #pragma unroll
        for (int j = 0; j < 8; ++j) {
            int cj = (j + 2 * q) & 7;
            int c  = 8 * q + cj;                       // 16B chunk in row (0..31)
            uint32_t roff = (uint32_t)(r * 512 + ((c ^ (r & 7)) << 4));
            float4 a  = *(const float4*)(sm + RAWA  + roff);
            float4 w  = *(const float4*)(sm + RAWW  + roff);
            float4 cm = *(const float4*)(sm + TILES + roff);
            om[4 * j + 0] = fmaf(h, fmaf(tm, w.x, a.x), cm.x);
            om[4 * j + 1] = fmaf(h, fmaf(tm, w.y, a.y), cm.y);
            om[4 * j + 2] = fmaf(h, fmaf(tm, w.z, a.z), cm.z);
            om[4 * j + 3] = fmaf(h, fmaf(tm, w.w, a.w), cm.w);
        }
        __syncthreads();   // raw reads done -> safe to prefetch next batch

        if (b + step < B) {
            const char* sA = (const char*)(A0 + (size_t)(b + step) * BD);
            const char* sW = (const char*)(Wm + (size_t)(b + step) * BD);
            #pragma unroll
            for (int it = 0; it < 8; ++it) {
                int i = tid + 512 * it;
                int row = i >> 5, ch = i & 31;
                uint32_t off = (uint32_t)(row * 512 + ((ch ^ (row & 7)) << 4));
                cp16(sb + RAWA + off, sA + (size_t)i * 16);
                cp16(sb + RAWW + off, sW + (size_t)i * 16);
            }
            asm volatile("cp.async.commit_group;" ::: "memory");
        }

        // ---- Phase E: y = expm(Omega) @ y0, 10-term Taylor ----
        float yvreg = v[r];
        #pragma unroll 1
        for (int k = 1; k <= 10; ++k) {
            float s0 = 0.f, s1 = 0.f, s2 = 0.f, s3 = 0.f;
            #pragma unroll
            for (int j = 0; j < 8; ++j) {
                int cj = (j + 2 * q) & 7;
                float4 f = *(const float4*)(sm + VOFF + q * 128 + cj * 16);
                s0 = fmaf(om[4 * j + 0], f.x, s0);
                s1 = fmaf(om[4 * j + 1], f.y, s1);
                s2 = fmaf(om[4 * j + 2], f.z, s2);
                s3 = fmaf(om[4 * j + 3], f.w, s3);
            }
            ps[r * 4 + q] = (s0 + s1) + (s2 + s3);
            __syncthreads();
            float4 p = *(const float4*)(ps + r * 4);
            float nv = ((p.x + p.y) + (p.z + p.w)) * (1.0f / (float)k);
            yvreg += nv;
            if (q == 0) v[r] = nv;
            __syncthreads();
        }
        if (q == 0) out[(size_t)b * DD + r] = yvreg;
    }
}

extern "C" void kernel_launch(void* const* d_in, const int* in_sizes, int n_in,
                              void* d_out, int out_size) {
    const float* t0 = (const float*)d_in[0];
    const float* h  = (const float*)d_in[1];
    const float* y0 = (const float*)d_in[2];
    const float* A0 = (const float*)d_in[3];
    const float* W  = (const float*)d_in[4];
    const int B = in_sizes[0];

    int grid = B < 152 ? B : 152;
    cudaFuncSetAttribute(magnus_kernel, cudaFuncAttributeMaxDynamicSharedMemorySize, SMEM_REQ);
    magnus_kernel<<<grid, 512, SMEM_REQ>>>(t0, h, y0, A0, W, (float*)d_out, B);
}